// round 16
// baseline (speedup 1.0000x reference)
#include <cuda_runtime.h>
#include <cuda_bf16.h>

#define NX 192
#define NY 192
#define NZ 192
#define NXY (NX * NY)

#define VEC 2                    // float2 per thread in x
#define SEGW (32 * VEC)          // 64 x per warp
#define WYD 4                    // 4 warps/CTA, 1 y-row each
#define NTHREADS 128
#define ZCHUNK 32                // multiple of 4
#define GXB (NX / SEGW)          // 3
#define GYB (NY / WYD)           // 48
#define GZB (NZ / ZCHUNK)        // 6
#define NBLOCKS (GXB * GYB * GZB) // 864 (single wave at 6 CTAs/SM)

#define FULLMASK 0xFFFFFFFFu

__device__ double g_acc = 0.0;
__device__ unsigned int g_done = 0;

// From preloaded row float2 v[3] (+ edge scalars e[3] for lanes 0/31),
// compute this thread's 2-element plane stats:
//   gx = sum_dy [v(x+1)-v(x-1)], gy = rowsum(y+1)-rowsum(y-1), b = 3x3 box
__device__ __forceinline__ void rows_stats(
    const float2* __restrict__ v, const float* __restrict__ e, int lane,
    float& gx0, float& gx1, float& gy0, float& gy1, float& b0, float& b1)
{
    float h0[3], h1[3], d0s = 0.f, d1s = 0.f;
#pragma unroll
    for (int r = 0; r < 3; ++r) {
        float l  = __shfl_up_sync(FULLMASK, v[r].y, 1);
        float rr = __shfl_down_sync(FULLMASK, v[r].x, 1);
        if (lane == 0)  l  = e[r];
        if (lane == 31) rr = e[r];
        float s = v[r].x + v[r].y;
        h0[r] = l + s;
        h1[r] = s + rr;
        d0s += v[r].y - l;
        d1s += rr - v[r].x;
    }
    gx0 = d0s;
    gx1 = d1s;
    gy0 = h0[2] - h0[0];
    gy1 = h1[2] - h1[0];
    b0  = h0[0] + h0[1] + h0[2];
    b1  = h1[0] + h1[1] + h1[2];
}

// One z-step. Slot `o` = stats(z-1), `m` = stats(z). Consumes the plane at
// pI/pJ (== z+1) and the mask row at mp (== plane z); bumps all pointers.
// Loads batched up front (the R11 scheduling that reached 55.8% issue).
#define STEP(o, m)                                                            \
    {                                                                         \
        float2 vI[3], vJ[3];                                                  \
        float  eI[3], eJ[3];                                                  \
        _Pragma("unroll")                                                     \
        for (int r = 0; r < 3; ++r)                                           \
            vI[r] = *reinterpret_cast<const float2*>(pI + co[r]);             \
        _Pragma("unroll")                                                     \
        for (int r = 0; r < 3; ++r)                                           \
            vJ[r] = *reinterpret_cast<const float2*>(pJ + co[r]);             \
        float2 m2 = *reinterpret_cast<const float2*>(mp);                     \
        if (edge) {                                                           \
            _Pragma("unroll")                                                 \
            for (int r = 0; r < 3; ++r) {                                     \
                eI[r] = pI[co[r] + dxe];                                      \
                eJ[r] = pJ[co[r] + dxe];                                      \
            }                                                                 \
        }                                                                     \
        float ngxI0, ngxI1, ngyI0, ngyI1, nbI0, nbI1;                         \
        float ngxJ0, ngxJ1, ngyJ0, ngyJ1, nbJ0, nbJ1;                         \
        rows_stats(vI, eI, lane, ngxI0, ngxI1, ngyI0, ngyI1, nbI0, nbI1);     \
        rows_stats(vJ, eJ, lane, ngxJ0, ngxJ1, ngyJ0, ngyJ1, nbJ0, nbJ1);     \
        {                                                                     \
            float Ix = gxI[o][0] + gxI[m][0] + ngxI0;                         \
            float Iy = gyI[o][0] + gyI[m][0] + ngyI0;                         \
            float Iz = nbI0 - bI[o][0];                                       \
            float Jx = gxJ[o][0] + gxJ[m][0] + ngxJ0;                         \
            float Jy = gyJ[o][0] + gyJ[m][0] + ngyJ0;                         \
            float Jz = nbJ0 - bJ[o][0];                                       \
            float ssi  = fmaf(Ix, Ix, fmaf(Iy, Iy, Iz * Iz));                 \
            float ssj  = fmaf(Jx, Jx, fmaf(Jy, Jy, Jz * Jz));                 \
            float sdot = fmaf(Ix, Jx, fmaf(Iy, Jy, Iz * Jz));                 \
            float ngf  = __fdividef(sdot * sdot,                              \
                                    (ssi + 0.04f) * (ssj + 0.04f));           \
            acc0 = fmaf(1.0f - ngf, m2.x, acc0);                              \
        }                                                                     \
        {                                                                     \
            float Ix = gxI[o][1] + gxI[m][1] + ngxI1;                         \
            float Iy = gyI[o][1] + gyI[m][1] + ngyI1;                         \
            float Iz = nbI1 - bI[o][1];                                       \
            float Jx = gxJ[o][1] + gxJ[m][1] + ngxJ1;                         \
            float Jy = gyJ[o][1] + gyJ[m][1] + ngyJ1;                         \
            float Jz = nbJ1 - bJ[o][1];                                       \
            float ssi  = fmaf(Ix, Ix, fmaf(Iy, Iy, Iz * Iz));                 \
            float ssj  = fmaf(Jx, Jx, fmaf(Jy, Jy, Jz * Jz));                 \
            float sdot = fmaf(Ix, Jx, fmaf(Iy, Jy, Iz * Jz));                 \
            float ngf  = __fdividef(sdot * sdot,                              \
                                    (ssi + 0.04f) * (ssj + 0.04f));           \
            acc1 = fmaf(1.0f - ngf, m2.y, acc1);                              \
        }                                                                     \
        gxI[o][0] = ngxI0; gxI[o][1] = ngxI1;                                 \
        gyI[o][0] = ngyI0; gyI[o][1] = ngyI1;                                 \
        bI[o][0]  = nbI0;  bI[o][1]  = nbI1;                                  \
        gxJ[o][0] = ngxJ0; gxJ[o][1] = ngxJ1;                                 \
        gyJ[o][0] = ngyJ0; gyJ[o][1] = ngyJ1;                                 \
        bJ[o][0]  = nbJ0;  bJ[o][1]  = nbJ1;                                  \
        pI += NXY; pJ += NXY; mp += NXY;                                      \
    }

__global__ __launch_bounds__(NTHREADS, 6)
void ngf_kernel(const float* __restrict__ I,
                const float* __restrict__ J,
                const float* __restrict__ M,
                float* __restrict__ out)
{
    __shared__ float warp_sums[WYD];

    const int lane = threadIdx.x;
    const int wy   = threadIdx.y;
    const int tid  = wy * 32 + lane;
    const int seg  = blockIdx.x;
    const int x2   = seg * SEGW + lane * VEC;
    const int y    = blockIdx.y * WYD + wy;
    const int z0   = blockIdx.z * ZCHUNK;

    const bool edge = (lane == 0) || (lane == 31);
    // Edge-lane neighbor offset relative to the float2 base (0/1 = clamp)
    int dxe = 0;
    if (lane == 0)  dxe = (x2 > 0) ? -1 : 0;
    if (lane == 31) dxe = (x2 + VEC < NX) ? 2 : 1;

    // Clamped (y-row*NX + x2) offsets, constant across z
    int co[3];
#pragma unroll
    for (int r = 0; r < 3; ++r) {
        int gy = y - 1 + r;
        gy = gy < 0 ? 0 : (gy > NY - 1 ? NY - 1 : gy);
        co[r] = gy * NX + x2;
    }

    // 2-slot rolling z-state: [0]/[1] alternate as (z-1)/(z) per step phase
    float gxI[2][VEC], gyI[2][VEC], bI[2][VEC];
    float gxJ[2][VEC], gyJ[2][VEC], bJ[2][VEC];

    // Prologue: plane z0-1 (clamped) -> slot 0, plane z0 -> slot 1
    {
        int gzm = z0 - 1 < 0 ? 0 : z0 - 1;
#pragma unroll
        for (int s = 0; s < 2; ++s) {
            size_t zoff = (size_t)(s == 0 ? gzm : z0) * NXY;
            const float* qI = I + zoff;
            const float* qJ = J + zoff;
            float2 vI[3], vJ[3];
            float  eI[3], eJ[3];
#pragma unroll
            for (int r = 0; r < 3; ++r) {
                vI[r] = *reinterpret_cast<const float2*>(qI + co[r]);
                vJ[r] = *reinterpret_cast<const float2*>(qJ + co[r]);
            }
            if (edge) {
#pragma unroll
                for (int r = 0; r < 3; ++r) {
                    eI[r] = qI[co[r] + dxe];
                    eJ[r] = qJ[co[r] + dxe];
                }
            }
            rows_stats(vI, eI, lane, gxI[s][0], gxI[s][1],
                       gyI[s][0], gyI[s][1], bI[s][0], bI[s][1]);
            rows_stats(vJ, eJ, lane, gxJ[s][0], gxJ[s][1],
                       gyJ[s][0], gyJ[s][1], bJ[s][0], bJ[s][1]);
        }
    }

    float acc0 = 0.0f, acc1 = 0.0f;

    // Streaming pointers: step k consumes plane z0+k+1 (I/J) and mask z0+k.
    const float* pI = I + (size_t)(z0 + 1) * NXY;
    const float* pJ = J + (size_t)(z0 + 1) * NXY;
    const float* mp = M + (size_t)z0 * NXY + co[1];   // co[1] == y*NX + x2

    // Steps 0 .. ZCHUNK-5, 4-step unrolled (the R11 scheduling win)
    for (int kb = 0; kb < ZCHUNK - 4; kb += 4) {
        STEP(0, 1)
        STEP(1, 0)
        STEP(0, 1)
        STEP(1, 0)
    }
    STEP(0, 1)
    STEP(1, 0)
    STEP(0, 1)
    // Final step would read plane NZ in the last z-block -> clamp to NZ-1.
    if (z0 + ZCHUNK >= NZ) { pI -= NXY; pJ -= NXY; }
    STEP(1, 0)

    float acc = acc0 + acc1;

    // Block reduction
#pragma unroll
    for (int off = 16; off > 0; off >>= 1)
        acc += __shfl_xor_sync(FULLMASK, acc, off);
    if (lane == 0) warp_sums[wy] = acc;
    __syncthreads();

    if (tid == 0) {
        float v = warp_sums[0] + warp_sums[1] + warp_sums[2] + warp_sums[3];
        atomicAdd(&g_acc, (double)v);
        __threadfence();
        unsigned prev = atomicAdd(&g_done, 1u);
        if (prev == NBLOCKS - 1) {
            // All other blocks' g_acc adds are fenced before their g_done
            // increments, so an atomic read here sees the full sum.
            double tot = atomicAdd(&g_acc, 0.0);
            out[0] = (float)(tot * (1.0 / (double)((long long)NX * NY * NZ)));
            g_acc = 0.0;       // reset for next replay (deterministic)
            __threadfence();
            g_done = 0;
        }
    }
}

extern "C" void kernel_launch(void* const* d_in, const int* in_sizes, int n_in,
                              void* d_out, int out_size) {
    const float* I = (const float*)d_in[0];
    const float* J = (const float*)d_in[1];
    const float* M = (const float*)d_in[2];
    float* out = (float*)d_out;

    dim3 block(32, WYD, 1);
    dim3 grid(GXB, GYB, GZB);   // 3 x 48 x 6 = 864 CTAs
    ngf_kernel<<<grid, block>>>(I, J, M, out);
}

// round 17
// speedup vs baseline: 1.1289x; 1.1289x over previous
#include <cuda_runtime.h>
#include <cuda_bf16.h>

#define NX 192
#define NY 192
#define NZ 192
#define NXY (NX * NY)

#define VEC 2                    // float2 per thread in x
#define SEGW (32 * VEC)          // 64 x per warp
#define WYD 4                    // 4 warps/CTA, 1 y-row each
#define NTHREADS 128
#define ZCHUNK 32                // multiple of 4
#define GXB (NX / SEGW)          // 3
#define GYB (NY / WYD)           // 48
#define GZB (NZ / ZCHUNK)        // 6
#define NBLOCKS (GXB * GYB * GZB) // 864 (single wave at 6 CTAs/SM)

#define FULLMASK 0xFFFFFFFFu

__device__ double g_acc = 0.0;
__device__ unsigned int g_done = 0;

// From preloaded row float2 v[3] (+ edge scalars e[3] for lanes 0/31),
// compute this thread's 2-element plane stats:
//   gx = sum_dy [v(x+1)-v(x-1)], gy = rowsum(y+1)-rowsum(y-1), b = 3x3 box
__device__ __forceinline__ void rows_stats(
    const float2* __restrict__ v, const float* __restrict__ e, int lane,
    float& gx0, float& gx1, float& gy0, float& gy1, float& b0, float& b1)
{
    float h0[3], h1[3], d0s = 0.f, d1s = 0.f;
#pragma unroll
    for (int r = 0; r < 3; ++r) {
        float l  = __shfl_up_sync(FULLMASK, v[r].y, 1);
        float rr = __shfl_down_sync(FULLMASK, v[r].x, 1);
        if (lane == 0)  l  = e[r];
        if (lane == 31) rr = e[r];
        float s = v[r].x + v[r].y;
        h0[r] = l + s;
        h1[r] = s + rr;
        d0s += v[r].y - l;
        d1s += rr - v[r].x;
    }
    gx0 = d0s;
    gx1 = d1s;
    gy0 = h0[2] - h0[0];
    gy1 = h1[2] - h1[0];
    b0  = h0[0] + h0[1] + h0[2];
    b1  = h1[0] + h1[1] + h1[2];
}

// One z-step. Slot `o` = stats(z-1), `m` = stats(z). PI/PJ are pointer
// EXPRESSIONS (group base + compile-time plane offset) -> each step's load
// addresses are independent of every other step's (no loop-carried chain),
// which is what keeps issue% high (R11 finding; R16 counterexample).
#define STEP(o, m, PI, PJ)                                                    \
    {                                                                         \
        const float* qI = (PI);                                               \
        const float* qJ = (PJ);                                               \
        float2 vI[3], vJ[3];                                                  \
        float  eI[3], eJ[3];                                                  \
        _Pragma("unroll")                                                     \
        for (int r = 0; r < 3; ++r)                                           \
            vI[r] = *reinterpret_cast<const float2*>(qI + co[r]);             \
        _Pragma("unroll")                                                     \
        for (int r = 0; r < 3; ++r)                                           \
            vJ[r] = *reinterpret_cast<const float2*>(qJ + co[r]);             \
        float2 m2 = *reinterpret_cast<const float2*>(mp);                     \
        if (edge) {                                                           \
            _Pragma("unroll")                                                 \
            for (int r = 0; r < 3; ++r) {                                     \
                eI[r] = qI[co[r] + dxe];                                      \
                eJ[r] = qJ[co[r] + dxe];                                      \
            }                                                                 \
        }                                                                     \
        float ngxI0, ngxI1, ngyI0, ngyI1, nbI0, nbI1;                         \
        float ngxJ0, ngxJ1, ngyJ0, ngyJ1, nbJ0, nbJ1;                         \
        rows_stats(vI, eI, lane, ngxI0, ngxI1, ngyI0, ngyI1, nbI0, nbI1);     \
        rows_stats(vJ, eJ, lane, ngxJ0, ngxJ1, ngyJ0, ngyJ1, nbJ0, nbJ1);     \
        {                                                                     \
            float Ix = gxI[o][0] + gxI[m][0] + ngxI0;                         \
            float Iy = gyI[o][0] + gyI[m][0] + ngyI0;                         \
            float Iz = nbI0 - bI[o][0];                                       \
            float Jx = gxJ[o][0] + gxJ[m][0] + ngxJ0;                         \
            float Jy = gyJ[o][0] + gyJ[m][0] + ngyJ0;                         \
            float Jz = nbJ0 - bJ[o][0];                                       \
            float ssi  = fmaf(Ix, Ix, fmaf(Iy, Iy, Iz * Iz));                 \
            float ssj  = fmaf(Jx, Jx, fmaf(Jy, Jy, Jz * Jz));                 \
            float sdot = fmaf(Ix, Jx, fmaf(Iy, Jy, Iz * Jz));                 \
            float ngf  = __fdividef(sdot * sdot,                              \
                                    (ssi + 0.04f) * (ssj + 0.04f));           \
            acc0 = fmaf(1.0f - ngf, m2.x, acc0);                              \
        }                                                                     \
        {                                                                     \
            float Ix = gxI[o][1] + gxI[m][1] + ngxI1;                         \
            float Iy = gyI[o][1] + gyI[m][1] + ngyI1;                         \
            float Iz = nbI1 - bI[o][1];                                       \
            float Jx = gxJ[o][1] + gxJ[m][1] + ngxJ1;                         \
            float Jy = gyJ[o][1] + gyJ[m][1] + ngyJ1;                         \
            float Jz = nbJ1 - bJ[o][1];                                       \
            float ssi  = fmaf(Ix, Ix, fmaf(Iy, Iy, Iz * Iz));                 \
            float ssj  = fmaf(Jx, Jx, fmaf(Jy, Jy, Jz * Jz));                 \
            float sdot = fmaf(Ix, Jx, fmaf(Iy, Jy, Iz * Jz));                 \
            float ngf  = __fdividef(sdot * sdot,                              \
                                    (ssi + 0.04f) * (ssj + 0.04f));           \
            acc1 = fmaf(1.0f - ngf, m2.y, acc1);                              \
        }                                                                     \
        gxI[o][0] = ngxI0; gxI[o][1] = ngxI1;                                 \
        gyI[o][0] = ngyI0; gyI[o][1] = ngyI1;                                 \
        bI[o][0]  = nbI0;  bI[o][1]  = nbI1;                                  \
        gxJ[o][0] = ngxJ0; gxJ[o][1] = ngxJ1;                                 \
        gyJ[o][0] = ngyJ0; gyJ[o][1] = ngyJ1;                                 \
        bJ[o][0]  = nbJ0;  bJ[o][1]  = nbJ1;                                  \
        mp += NXY;                                                            \
    }

__global__ __launch_bounds__(NTHREADS, 6)
void ngf_kernel(const float* __restrict__ I,
                const float* __restrict__ J,
                const float* __restrict__ M,
                float* __restrict__ out)
{
    __shared__ float warp_sums[WYD];

    const int lane = threadIdx.x;
    const int wy   = threadIdx.y;
    const int tid  = wy * 32 + lane;
    const int seg  = blockIdx.x;
    const int x2   = seg * SEGW + lane * VEC;
    const int y    = blockIdx.y * WYD + wy;
    const int z0   = blockIdx.z * ZCHUNK;

    const bool edge = (lane == 0) || (lane == 31);
    // Edge-lane neighbor offset relative to the float2 base (0/1 = clamp)
    int dxe = 0;
    if (lane == 0)  dxe = (x2 > 0) ? -1 : 0;
    if (lane == 31) dxe = (x2 + VEC < NX) ? 2 : 1;

    // Clamped (y-row*NX + x2) offsets, constant across z
    int co[3];
#pragma unroll
    for (int r = 0; r < 3; ++r) {
        int gy = y - 1 + r;
        gy = gy < 0 ? 0 : (gy > NY - 1 ? NY - 1 : gy);
        co[r] = gy * NX + x2;
    }

    // 2-slot rolling z-state: [0]/[1] alternate as (z-1)/(z) per step phase
    float gxI[2][VEC], gyI[2][VEC], bI[2][VEC];
    float gxJ[2][VEC], gyJ[2][VEC], bJ[2][VEC];

    // Prologue: plane z0-1 (clamped) -> slot 0, plane z0 -> slot 1
    {
        int gzm = z0 - 1 < 0 ? 0 : z0 - 1;
#pragma unroll
        for (int s = 0; s < 2; ++s) {
            size_t zoff = (size_t)(s == 0 ? gzm : z0) * NXY;
            const float* qI = I + zoff;
            const float* qJ = J + zoff;
            float2 vI[3], vJ[3];
            float  eI[3], eJ[3];
#pragma unroll
            for (int r = 0; r < 3; ++r) {
                vI[r] = *reinterpret_cast<const float2*>(qI + co[r]);
                vJ[r] = *reinterpret_cast<const float2*>(qJ + co[r]);
            }
            if (edge) {
#pragma unroll
                for (int r = 0; r < 3; ++r) {
                    eI[r] = qI[co[r] + dxe];
                    eJ[r] = qJ[co[r] + dxe];
                }
            }
            rows_stats(vI, eI, lane, gxI[s][0], gxI[s][1],
                       gyI[s][0], gyI[s][1], bI[s][0], bI[s][1]);
            rows_stats(vJ, eJ, lane, gxJ[s][0], gxJ[s][1],
                       gyJ[s][0], gyJ[s][1], bJ[s][0], bJ[s][1]);
        }
    }

    float acc0 = 0.0f, acc1 = 0.0f;

    // Mask row pointer (streaming is fine for the single mask load; the
    // plane loads must stay base+immediate-indexed).
    const float* mp = M + (size_t)z0 * NXY + co[1];   // co[1] == y*NX + x2

    // Steps 0 .. ZCHUNK-5, grouped by 4: one group base, compile-time plane
    // offsets u*NXY -> all 4 steps' loads are address-independent.
    for (int kb = 0; kb < ZCHUNK - 4; kb += 4) {
        const float* pIb = I + (size_t)(z0 + 1 + kb) * NXY;
        const float* pJb = J + (size_t)(z0 + 1 + kb) * NXY;
        STEP(0, 1, pIb,           pJb)
        STEP(1, 0, pIb + NXY,     pJb + NXY)
        STEP(0, 1, pIb + 2 * NXY, pJb + 2 * NXY)
        STEP(1, 0, pIb + 3 * NXY, pJb + 3 * NXY)
    }
    // Peeled final group (steps ZCHUNK-4 .. ZCHUNK-1). The last step reads
    // plane z0+ZCHUNK which the last z-block clamps to NZ-1 (offset 2 not 3).
    {
        const float* pIb = I + (size_t)(z0 + ZCHUNK - 3) * NXY;
        const float* pJb = J + (size_t)(z0 + ZCHUNK - 3) * NXY;
        STEP(0, 1, pIb,           pJb)
        STEP(1, 0, pIb + NXY,     pJb + NXY)
        STEP(0, 1, pIb + 2 * NXY, pJb + 2 * NXY)
        const size_t lu = (z0 + ZCHUNK >= NZ) ? (size_t)(2 * NXY)
                                              : (size_t)(3 * NXY);
        STEP(1, 0, pIb + lu,      pJb + lu)
    }

    float acc = acc0 + acc1;

    // Block reduction
#pragma unroll
    for (int off = 16; off > 0; off >>= 1)
        acc += __shfl_xor_sync(FULLMASK, acc, off);
    if (lane == 0) warp_sums[wy] = acc;
    __syncthreads();

    if (tid == 0) {
        float v = warp_sums[0] + warp_sums[1] + warp_sums[2] + warp_sums[3];
        atomicAdd(&g_acc, (double)v);
        __threadfence();
        unsigned prev = atomicAdd(&g_done, 1u);
        if (prev == NBLOCKS - 1) {
            // All other blocks' g_acc adds are fenced before their g_done
            // increments, so an atomic read here sees the full sum.
            double tot = atomicAdd(&g_acc, 0.0);
            out[0] = (float)(tot * (1.0 / (double)((long long)NX * NY * NZ)));
            g_acc = 0.0;       // reset for next replay (deterministic)
            __threadfence();
            g_done = 0;
        }
    }
}

extern "C" void kernel_launch(void* const* d_in, const int* in_sizes, int n_in,
                              void* d_out, int out_size) {
    const float* I = (const float*)d_in[0];
    const float* J = (const float*)d_in[1];
    const float* M = (const float*)d_in[2];
    float* out = (float*)d_out;

    dim3 block(32, WYD, 1);
    dim3 grid(GXB, GYB, GZB);   // 3 x 48 x 6 = 864 CTAs
    ngf_kernel<<<grid, block>>>(I, J, M, out);
}